// round 1
// baseline (speedup 1.0000x reference)
#include <cuda_runtime.h>
#include <cstdint>

// ---------------- problem constants ----------------
#define WW 512
#define HH 512
#define HWSZ (512*512)          // 262144
#define BN 8
#define NPLANE (BN*HWSZ)        // 2,097,152
#define NCH 24                  // B*3

// ---------------- scratch (device globals; no allocs allowed) ----------------
__device__ float g_t0[NPLANE];      // t0, later reused for 'a'
__device__ float g_gray[NPLANE];
__device__ float g_tg[NPLANE];      // tg, later reused for 'b'
__device__ float g_h0[NPLANE];      // hbox sums / later ha
__device__ float g_h1[NPLANE];      // hbox sums / later hb
__device__ float g_h2[NPLANE];      // hbox sums / later t_final
__device__ float g_h3[NPLANE];
__device__ float g_J[3*NPLANE];

__device__ unsigned g_hist1[NCH][4096];
__device__ unsigned g_hist2[NCH][2][4096];
__device__ unsigned g_hist3[NCH][2][256];
__device__ unsigned g_bin1[NCH][2];
__device__ unsigned g_rank1[NCH][2];
__device__ unsigned g_pre2[NCH][2];
__device__ unsigned g_rank2[NCH][2];
__device__ float    g_pvals[NCH][2];

__device__ __forceinline__ int refl(int i, int n) {
    i = (i < 0) ? -i : i;
    return (i >= n) ? (2*n - 2 - i) : i;
}
__device__ __forceinline__ int clampr(int r) {
    if (r < 1) r = 1;
    if (r > 50) r = 50;
    return r;
}

// ---------------- K0: zero histograms ----------------
__global__ void k_zero() {
    int idx = blockIdx.x * blockDim.x + threadIdx.x;
    unsigned* h1 = &g_hist1[0][0];
    unsigned* h2 = &g_hist2[0][0][0];
    unsigned* h3 = &g_hist3[0][0][0];
    if (idx < NCH*4096)   h1[idx] = 0;
    if (idx < NCH*2*4096) h2[idx] = 0;
    if (idx < NCH*2*256)  h3[idx] = 0;
}

// ---------------- K1: t0 and gray ----------------
__global__ void k_t0_gray(const float* __restrict__ img,
                          const float* __restrict__ omega,
                          const float* __restrict__ atm) {
    int idx = blockIdx.x * blockDim.x + threadIdx.x;
    if (idx >= NPLANE) return;
    int b = idx >> 18;           // /HWSZ
    int p = idx & (HWSZ - 1);
    const float* ib = img + (size_t)b * 3 * HWSZ + p;
    float a0 = atm[b*3+0], a1 = atm[b*3+1], a2 = atm[b*3+2];
    float r_ = ib[0], gch = ib[HWSZ], bch = ib[2*HWSZ];
    float d0 = r_  / (a0 + 1e-8f);
    float d1 = gch / (a1 + 1e-8f);
    float d2 = bch / (a2 + 1e-8f);
    float dark = fminf(d0, fminf(d1, d2));
    g_t0[idx]   = 1.0f - omega[b] * dark;
    g_gray[idx] = 0.299f*r_ + 0.587f*gch + 0.114f*bch;
}

// ---------------- K2: gradient-constrained tg ----------------
__global__ void k_tg() {
    int idx = blockIdx.x * blockDim.x + threadIdx.x;
    if (idx >= NPLANE) return;
    int b = idx >> 18;
    int p = idx & (HWSZ - 1);
    int y = p >> 9, x = p & 511;
    const float* T = g_t0 + b * HWSZ;
    int yp = (y == 0) ? 0 : (y - 1);
    float txv;
    if (x == 0) {
        txv = T[yp*WW];
    } else {
        float a = T[yp*WW + x], c = T[yp*WW + x - 1];
        txv = c * expf(-fabsf(a - c));
    }
    float tgv = txv;
    if (y > 0) {
        float a = T[y*WW + x], c = T[(y-1)*WW + x];
        tgv = txv * expf(-fabsf(a - c));
    }
    g_tg[idx] = tgv;
}

// ---------------- K3: horizontal box sums of {gray, tg, gray*tg, gray^2} ----------------
__global__ void k_hbox4(const int* __restrict__ rp) {
    int r = clampr(rp[0]);
    int row = blockIdx.x;            // b*H + y
    int b = row >> 9, y = row & 511;
    __shared__ float sg[612], st[612];
    int base = b * HWSZ + y * WW;
    int pw = WW + 2*r;
    for (int i = threadIdx.x; i < pw; i += blockDim.x) {
        int x = refl(i - r, WW);
        sg[i] = g_gray[base + x];
        st[i] = g_tg[base + x];
    }
    __syncthreads();
    int x = threadIdx.x;             // blockDim = 512
    float s1 = 0.f, s2 = 0.f, s3 = 0.f, s4 = 0.f;
    int k = 2*r + 1;
    for (int d = 0; d < k; d++) {
        float gv = sg[x+d], tv = st[x+d];
        s1 += gv; s2 += tv; s3 += gv*tv; s4 += gv*gv;
    }
    g_h0[base+x] = s1; g_h1[base+x] = s2; g_h2[base+x] = s3; g_h3[base+x] = s4;
}

// ---------------- K4: vertical box (sliding) + a,b ----------------
#define SEG 64
__global__ void k_vbox4(const int* __restrict__ rp) {
    int r = clampr(rp[0]);
    int k = 2*r + 1;
    float inv = 1.0f / ((float)k * (float)k);
    int t = blockIdx.x * blockDim.x + threadIdx.x;
    if (t >= BN * WW * (HH/SEG)) return;
    int x = t & 511;
    int q = t >> 9;
    int b = q & 7;
    int seg = q >> 3;
    int y0 = seg * SEG;
    const float* p0 = g_h0 + b*HWSZ + x;
    const float* p1 = g_h1 + b*HWSZ + x;
    const float* p2 = g_h2 + b*HWSZ + x;
    const float* p3 = g_h3 + b*HWSZ + x;
    float s0 = 0.f, s1 = 0.f, s2 = 0.f, s3 = 0.f;
    for (int d = -r; d <= r; d++) {
        int off = refl(y0 + d, HH) * WW;
        s0 += p0[off]; s1 += p1[off]; s2 += p2[off]; s3 += p3[off];
    }
    float* pa = g_t0 + b*HWSZ + x;   // 'a'
    float* pb = g_tg + b*HWSZ + x;   // 'b'
    for (int y = y0; y < y0 + SEG; y++) {
        float mI  = s0*inv, mp  = s1*inv;
        float mIp = s2*inv, mII = s3*inv;
        float cov = mIp - mI*mp;
        float var = mII - mI*mI;
        float a = cov / (var + 0.5f);
        float bb = mp - a*mI;
        pa[y*WW] = a;
        pb[y*WW] = bb;
        int ya = refl(y + 1 + r, HH) * WW;
        int ys = refl(y - r, HH) * WW;
        s0 += p0[ya] - p0[ys];
        s1 += p1[ya] - p1[ys];
        s2 += p2[ya] - p2[ys];
        s3 += p3[ya] - p3[ys];
    }
}

// ---------------- K5: horizontal box sums of {a, b} ----------------
__global__ void k_hbox2(const int* __restrict__ rp) {
    int r = clampr(rp[0]);
    int row = blockIdx.x;
    int b = row >> 9, y = row & 511;
    __shared__ float sa[612], sb[612];
    int base = b * HWSZ + y * WW;
    int pw = WW + 2*r;
    for (int i = threadIdx.x; i < pw; i += blockDim.x) {
        int x = refl(i - r, WW);
        sa[i] = g_t0[base + x];
        sb[i] = g_tg[base + x];
    }
    __syncthreads();
    int x = threadIdx.x;
    float s1 = 0.f, s2 = 0.f;
    int k = 2*r + 1;
    for (int d = 0; d < k; d++) { s1 += sa[x+d]; s2 += sb[x+d]; }
    g_h0[base+x] = s1;
    g_h1[base+x] = s2;
}

// ---------------- K6: vertical box of {a,b} + t_final ----------------
__global__ void k_vbox2(const int* __restrict__ rp) {
    int r = clampr(rp[0]);
    int k = 2*r + 1;
    float inv = 1.0f / ((float)k * (float)k);
    int t = blockIdx.x * blockDim.x + threadIdx.x;
    if (t >= BN * WW * (HH/SEG)) return;
    int x = t & 511;
    int q = t >> 9;
    int b = q & 7;
    int seg = q >> 3;
    int y0 = seg * SEG;
    const float* p0 = g_h0 + b*HWSZ + x;
    const float* p1 = g_h1 + b*HWSZ + x;
    const float* pg = g_gray + b*HWSZ + x;
    float s0 = 0.f, s1 = 0.f;
    for (int d = -r; d <= r; d++) {
        int off = refl(y0 + d, HH) * WW;
        s0 += p0[off]; s1 += p1[off];
    }
    float* pt = g_h2 + b*HWSZ + x;   // t_final
    for (int y = y0; y < y0 + SEG; y++) {
        float tf = (s0*inv) * pg[y*WW] + (s1*inv);
        tf = fminf(fmaxf(tf, 0.1f), 1.0f);
        pt[y*WW] = tf;
        int ya = refl(y + 1 + r, HH) * WW;
        int ys = refl(y - r, HH) * WW;
        s0 += p0[ya] - p0[ys];
        s1 += p1[ya] - p1[ys];
    }
}

// ---------------- K7: restoration J + stage-1 histogram (key>>20) ----------------
__global__ void k_J_hist(const float* __restrict__ img,
                         const float* __restrict__ atm) {
    __shared__ unsigned sh[4096];
    int tid = threadIdx.x;
    for (int i = tid; i < 4096; i += 256) sh[i] = 0;
    __syncthreads();
    int bc = blockIdx.y;
    int b = bc / 3;
    float A = atm[bc];
    size_t base = (size_t)bc * HWSZ + (size_t)blockIdx.x * 4096;
    const float* ip = img + base;
    const float* tp = g_h2 + (size_t)b * HWSZ + (size_t)blockIdx.x * 4096;
    float* Jp = g_J + base;
    for (int i = 0; i < 16; i++) {
        int o = i*256 + tid;
        float iv = ip[o];
        float tf = tp[o];
        float Jv = (iv - A) / (tf + 1e-8f) + A;
        Jv = fminf(fmaxf(Jv, 0.0f), 1.0f);
        Jp[o] = Jv;
        atomicAdd(&sh[__float_as_uint(Jv) >> 20], 1u);
    }
    __syncthreads();
    for (int i = tid; i < 4096; i += 256)
        if (sh[i]) atomicAdd(&g_hist1[bc][i], sh[i]);
}

// ---------------- K8: stage-1 select ----------------
__global__ void k_sel1(const float* __restrict__ Llow,
                       const float* __restrict__ Lhigh) {
    int bc = blockIdx.x;
    int b = bc / 3;
    __shared__ unsigned part[256];
    for (int slot = 0; slot < 2; slot++) {
        float Lv = (slot == 0) ? Llow[b] : Lhigh[b];
        float qf = (Lv / 100.0f) * (float)HWSZ;
        int tgt = (int)qf;
        if (tgt < 0) tgt = 0;
        if (tgt > HWSZ - 1) tgt = HWSZ - 1;
        const unsigned* h = g_hist1[bc];
        unsigned s = 0;
        for (int j = 0; j < 16; j++) s += h[threadIdx.x*16 + j];
        part[threadIdx.x] = s;
        __syncthreads();
        if (threadIdx.x == 0) {
            unsigned cum = 0;
            int slice = 0;
            for (; slice < 256; slice++) {
                if (cum + part[slice] > (unsigned)tgt) break;
                cum += part[slice];
            }
            int bin = slice * 16;
            for (;; bin++) {
                if (cum + h[bin] > (unsigned)tgt) break;
                cum += h[bin];
            }
            g_bin1[bc][slot]  = (unsigned)bin;
            g_rank1[bc][slot] = (unsigned)tgt - cum;
        }
        __syncthreads();
    }
}

// ---------------- K9: stage-2 histogram ((key>>8)&0xFFF within selected top-12 bin) ----------------
__global__ void k_hist2() {
    __shared__ unsigned shL[4096], shH[4096];
    int tid = threadIdx.x;
    for (int i = tid; i < 4096; i += 256) { shL[i] = 0; shH[i] = 0; }
    __syncthreads();
    int bc = blockIdx.y;
    unsigned binL = g_bin1[bc][0];
    unsigned binH = g_bin1[bc][1];
    const float* Jp = g_J + (size_t)bc * HWSZ + (size_t)blockIdx.x * 4096;
    for (int i = 0; i < 16; i++) {
        unsigned key = __float_as_uint(Jp[i*256 + tid]);
        unsigned t12 = key >> 20;
        unsigned sub = (key >> 8) & 0xFFFu;
        if (t12 == binL) atomicAdd(&shL[sub], 1u);
        if (t12 == binH) atomicAdd(&shH[sub], 1u);
    }
    __syncthreads();
    for (int i = tid; i < 4096; i += 256) {
        if (shL[i]) atomicAdd(&g_hist2[bc][0][i], shL[i]);
        if (shH[i]) atomicAdd(&g_hist2[bc][1][i], shH[i]);
    }
}

// ---------------- K10: stage-2 select ----------------
__global__ void k_sel2() {
    int bc = blockIdx.x;
    __shared__ unsigned part[256];
    for (int slot = 0; slot < 2; slot++) {
        unsigned tgt = g_rank1[bc][slot];
        const unsigned* h = g_hist2[bc][slot];
        unsigned s = 0;
        for (int j = 0; j < 16; j++) s += h[threadIdx.x*16 + j];
        part[threadIdx.x] = s;
        __syncthreads();
        if (threadIdx.x == 0) {
            unsigned cum = 0;
            int slice = 0;
            for (; slice < 256; slice++) {
                if (cum + part[slice] > tgt) break;
                cum += part[slice];
            }
            int bin = slice * 16;
            for (;; bin++) {
                if (cum + h[bin] > tgt) break;
                cum += h[bin];
            }
            g_pre2[bc][slot]  = (g_bin1[bc][slot] << 12) | (unsigned)bin;
            g_rank2[bc][slot] = tgt - cum;
        }
        __syncthreads();
    }
}

// ---------------- K11: stage-3 histogram (key&0xFF within selected top-24 prefix) ----------------
__global__ void k_hist3() {
    __shared__ unsigned shL[256], shH[256];
    int tid = threadIdx.x;
    if (tid < 256) { shL[tid] = 0; shH[tid] = 0; }
    __syncthreads();
    int bc = blockIdx.y;
    unsigned preL = g_pre2[bc][0];
    unsigned preH = g_pre2[bc][1];
    const float* Jp = g_J + (size_t)bc * HWSZ + (size_t)blockIdx.x * 4096;
    for (int i = 0; i < 16; i++) {
        unsigned key = __float_as_uint(Jp[i*256 + tid]);
        unsigned pre = key >> 8;
        unsigned sub = key & 0xFFu;
        if (pre == preL) atomicAdd(&shL[sub], 1u);
        if (pre == preH) atomicAdd(&shH[sub], 1u);
    }
    __syncthreads();
    if (tid < 256) {
        if (shL[tid]) atomicAdd(&g_hist3[bc][0][tid], shL[tid]);
        if (shH[tid]) atomicAdd(&g_hist3[bc][1][tid], shH[tid]);
    }
}

// ---------------- K12: final select -> p_low / p_high ----------------
__global__ void k_sel3() {
    int bc = blockIdx.x;
    if (threadIdx.x == 0) {
        for (int slot = 0; slot < 2; slot++) {
            unsigned tgt = g_rank2[bc][slot];
            const unsigned* h = g_hist3[bc][slot];
            unsigned cum = 0;
            int bin = 0;
            for (; bin < 256; bin++) {
                if (cum + h[bin] > tgt) break;
                cum += h[bin];
            }
            unsigned key = (g_pre2[bc][slot] << 8) | (unsigned)bin;
            g_pvals[bc][slot] = __uint_as_float(key);
        }
    }
}

// ---------------- K13: final normalize ----------------
__global__ void k_out(float* __restrict__ out) {
    int idx = blockIdx.x * blockDim.x + threadIdx.x;
    if (idx >= 3*NPLANE) return;
    int bc = idx >> 18;
    float pl = g_pvals[bc][0];
    float ph = g_pvals[bc][1];
    float Jv = g_J[idx];
    float v = fminf(fmaxf(Jv, pl), ph);
    float o = (v - pl) / (ph - pl + 1e-8f);
    out[idx] = fminf(fmaxf(o, 0.0f), 1.0f);
}

// ---------------- launch ----------------
extern "C" void kernel_launch(void* const* d_in, const int* in_sizes, int n_in,
                              void* d_out, int out_size) {
    const float* img   = (const float*)d_in[0];
    const float* omega = (const float*)d_in[1];
    const float* atm   = (const float*)d_in[2];
    const float* Llow  = (const float*)d_in[3];
    const float* Lhigh = (const float*)d_in[4];
    const int*   rp    = (const int*)d_in[5];  // first 4 bytes hold the (small, positive) radius either way
    float* out = (float*)d_out;

    (void)in_sizes; (void)n_in; (void)out_size;

    k_zero<<<(NCH*2*4096 + 255)/256, 256>>>();
    k_t0_gray<<<NPLANE/256, 256>>>(img, omega, atm);
    k_tg<<<NPLANE/256, 256>>>();
    k_hbox4<<<BN*HH, 512>>>(rp);
    k_vbox4<<<(BN*WW*(HH/SEG))/256, 256>>>(rp);
    k_hbox2<<<BN*HH, 512>>>(rp);
    k_vbox2<<<(BN*WW*(HH/SEG))/256, 256>>>(rp);
    dim3 gJ(HWSZ/4096, NCH);
    k_J_hist<<<gJ, 256>>>(img, atm);
    k_sel1<<<NCH, 256>>>(Llow, Lhigh);
    k_hist2<<<gJ, 256>>>();
    k_sel2<<<NCH, 256>>>();
    k_hist3<<<gJ, 256>>>();
    k_sel3<<<NCH, 32>>>();
    k_out<<<(3*NPLANE)/256, 256>>>(out);
}

// round 3
// speedup vs baseline: 1.2105x; 1.2105x over previous
#include <cuda_runtime.h>
#include <cstdint>

// ---------------- problem constants ----------------
#define WW 512
#define HH 512
#define HWSZ (512*512)          // 262144
#define BN 8
#define NPLANE (BN*HWSZ)        // 2,097,152
#define NCH 24                  // B*3

// ---------------- scratch (device globals; no allocs allowed) ----------------
__device__ float g_a[NPLANE];       // 'a' from vbox4
__device__ float g_b[NPLANE];       // 'b' from vbox4
__device__ float g_gray[NPLANE];
__device__ float g_h0[NPLANE];      // hbox sums
__device__ float g_h1[NPLANE];
__device__ float g_h2[NPLANE];      // later t_final
__device__ float g_h3[NPLANE];
__device__ float g_J[3*NPLANE];

__device__ unsigned g_hist1[NCH][4096];
__device__ unsigned g_hist2[NCH][2][4096];
__device__ unsigned g_hist3[NCH][2][256];
__device__ unsigned g_bin1[NCH][2];
__device__ unsigned g_rank1[NCH][2];
__device__ unsigned g_pre2[NCH][2];
__device__ unsigned g_rank2[NCH][2];
__device__ float    g_pvals[NCH][2];

__device__ __forceinline__ int refl(int i, int n) {
    i = (i < 0) ? -i : i;
    return (i >= n) ? (2*n - 2 - i) : i;
}
__device__ __forceinline__ int clampr(int r) {
    if (r < 1) r = 1;
    if (r > 50) r = 50;
    return r;
}

// ============ K1: fused t0/gray/tg + horizontal box of 4 streams ============
// One block per (b,y) row. Computes t0 rows y-1,y from img, tg row y inline,
// gray row y (stored), then sliding-window horizontal box sums of
// {gray, tg, gray*tg, gray*gray}. Also zeroes g_hist1 (spread across blocks).
__global__ __launch_bounds__(128) void k_front(const float* __restrict__ img,
                                               const float* __restrict__ omega,
                                               const float* __restrict__ atm,
                                               const int* __restrict__ rp) {
    int r = clampr(rp[0]);
    int row = blockIdx.x;
    int b = row >> 9, y = row & 511;

    // zero hist1: 24*4096 entries over 4096 blocks = 24 each
    {
        unsigned* h1 = &g_hist1[0][0];
        int base = row * 24;
        for (int i = threadIdx.x; i < 24; i += 128) h1[base + i] = 0;
    }

    __shared__ float t0p[512], t0c[512];
    __shared__ float sg[612], st[612], sgt[612], sgg[612];

    float om = omega[b];
    float a0 = atm[b*3+0] + 1e-8f;
    float a1 = atm[b*3+1] + 1e-8f;
    float a2 = atm[b*3+2] + 1e-8f;
    const float* ib = img + (size_t)b * 3 * HWSZ;
    int yp = (y == 0) ? 0 : y - 1;
    int rowbase = b * HWSZ + y * WW;

    for (int x = threadIdx.x; x < 512; x += 128) {
        // t0 row y-1
        float rv = ib[yp*WW + x], gv = ib[HWSZ + yp*WW + x], bv = ib[2*HWSZ + yp*WW + x];
        float dark = fminf(rv/a0, fminf(gv/a1, bv/a2));
        t0p[x] = 1.0f - om * dark;
        // t0 row y + gray row y
        float rc = ib[y*WW + x], gc = ib[HWSZ + y*WW + x], bc = ib[2*HWSZ + y*WW + x];
        float darkc = fminf(rc/a0, fminf(gc/a1, bc/a2));
        t0c[x] = 1.0f - om * darkc;
        float gy = 0.299f*rc + 0.587f*gc + 0.114f*bc;
        sg[r + x] = gy;
        g_gray[rowbase + x] = gy;
    }
    __syncthreads();

    // tg row y
    for (int x = threadIdx.x; x < 512; x += 128) {
        float txv = (x == 0) ? t0p[0]
                             : t0p[x-1] * expf(-fabsf(t0p[x] - t0p[x-1]));
        float tgv = (y == 0) ? txv
                             : txv * expf(-fabsf(t0c[x] - t0p[x]));
        st[r + x] = tgv;
    }
    __syncthreads();

    // reflect halos for sg, st
    for (int i = threadIdx.x; i < r; i += 128) {
        sg[i] = sg[r + (r - i)];
        st[i] = st[r + (r - i)];
        sg[r + 512 + i] = sg[r + 510 - i];
        st[r + 512 + i] = st[r + 510 - i];
    }
    __syncthreads();

    int pw = 512 + 2*r;
    for (int i = threadIdx.x; i < pw; i += 128) {
        float g = sg[i], t = st[i];
        sgt[i] = g * t;
        sgg[i] = g * g;
    }
    __syncthreads();

    // sliding-window box sums: each thread does 4 consecutive outputs
    int x0 = threadIdx.x * 4;
    int k = 2*r + 1;
    float s0 = 0.f, s1 = 0.f, s2 = 0.f, s3 = 0.f;
    for (int d = 0; d < k; d++) {
        s0 += sg[x0+d]; s1 += st[x0+d]; s2 += sgt[x0+d]; s3 += sgg[x0+d];
    }
    float4 o0, o1, o2, o3;
    o0.x = s0; o1.x = s1; o2.x = s2; o3.x = s3;
    #pragma unroll
    for (int j = 1; j < 4; j++) {
        int add = x0 + k - 1 + j, sub = x0 + j - 1;
        s0 += sg[add] - sg[sub];
        s1 += st[add] - st[sub];
        s2 += sgt[add] - sgt[sub];
        s3 += sgg[add] - sgg[sub];
        ((float*)&o0)[j] = s0; ((float*)&o1)[j] = s1;
        ((float*)&o2)[j] = s2; ((float*)&o3)[j] = s3;
    }
    int base = rowbase + x0;
    *(float4*)(g_h0 + base) = o0;
    *(float4*)(g_h1 + base) = o1;
    *(float4*)(g_h2 + base) = o2;
    *(float4*)(g_h3 + base) = o3;
}

// ============ K2: vertical box (sliding) + a,b ============
#define SEG 64
__global__ void k_vbox4(const int* __restrict__ rp) {
    int r = clampr(rp[0]);
    int k = 2*r + 1;
    float inv = 1.0f / ((float)k * (float)k);
    int t = blockIdx.x * blockDim.x + threadIdx.x;
    if (t >= BN * WW * (HH/SEG)) return;
    int x = t & 511;
    int q = t >> 9;
    int b = q & 7;
    int seg = q >> 3;
    int y0 = seg * SEG;
    const float* p0 = g_h0 + b*HWSZ + x;
    const float* p1 = g_h1 + b*HWSZ + x;
    const float* p2 = g_h2 + b*HWSZ + x;
    const float* p3 = g_h3 + b*HWSZ + x;
    float s0 = 0.f, s1 = 0.f, s2 = 0.f, s3 = 0.f;
    for (int d = -r; d <= r; d++) {
        int off = refl(y0 + d, HH) * WW;
        s0 += p0[off]; s1 += p1[off]; s2 += p2[off]; s3 += p3[off];
    }
    float* pa = g_a + b*HWSZ + x;
    float* pb = g_b + b*HWSZ + x;
    for (int y = y0; y < y0 + SEG; y++) {
        float mI  = s0*inv, mp  = s1*inv;
        float mIp = s2*inv, mII = s3*inv;
        float cov = mIp - mI*mp;
        float var = mII - mI*mI;
        float a = cov / (var + 0.5f);
        float bb = mp - a*mI;
        pa[y*WW] = a;
        pb[y*WW] = bb;
        int ya = refl(y + 1 + r, HH) * WW;
        int ys = refl(y - r, HH) * WW;
        s0 += p0[ya] - p0[ys];
        s1 += p1[ya] - p1[ys];
        s2 += p2[ya] - p2[ys];
        s3 += p3[ya] - p3[ys];
    }
}

// ============ K3: horizontal box of {a,b} (sliding + coarsening) ============
__global__ __launch_bounds__(128) void k_hbox2(const int* __restrict__ rp) {
    int r = clampr(rp[0]);
    int row = blockIdx.x;
    int b = row >> 9, y = row & 511;
    __shared__ float sa[612], sb[612];
    int rowbase = b * HWSZ + y * WW;
    for (int x = threadIdx.x; x < 512; x += 128) {
        sa[r + x] = g_a[rowbase + x];
        sb[r + x] = g_b[rowbase + x];
    }
    __syncthreads();
    for (int i = threadIdx.x; i < r; i += 128) {
        sa[i] = sa[r + (r - i)];
        sb[i] = sb[r + (r - i)];
        sa[r + 512 + i] = sa[r + 510 - i];
        sb[r + 512 + i] = sb[r + 510 - i];
    }
    __syncthreads();
    int x0 = threadIdx.x * 4;
    int k = 2*r + 1;
    float s0 = 0.f, s1 = 0.f;
    for (int d = 0; d < k; d++) { s0 += sa[x0+d]; s1 += sb[x0+d]; }
    float4 o0, o1;
    o0.x = s0; o1.x = s1;
    #pragma unroll
    for (int j = 1; j < 4; j++) {
        int add = x0 + k - 1 + j, sub = x0 + j - 1;
        s0 += sa[add] - sa[sub];
        s1 += sb[add] - sb[sub];
        ((float*)&o0)[j] = s0; ((float*)&o1)[j] = s1;
    }
    *(float4*)(g_h0 + rowbase + x0) = o0;
    *(float4*)(g_h1 + rowbase + x0) = o1;
}

// ============ K4: vertical box of {a,b} + t_final ============
__global__ void k_vbox2(const int* __restrict__ rp) {
    int r = clampr(rp[0]);
    int k = 2*r + 1;
    float inv = 1.0f / ((float)k * (float)k);
    int t = blockIdx.x * blockDim.x + threadIdx.x;
    if (t >= BN * WW * (HH/SEG)) return;
    int x = t & 511;
    int q = t >> 9;
    int b = q & 7;
    int seg = q >> 3;
    int y0 = seg * SEG;
    const float* p0 = g_h0 + b*HWSZ + x;
    const float* p1 = g_h1 + b*HWSZ + x;
    const float* pg = g_gray + b*HWSZ + x;
    float s0 = 0.f, s1 = 0.f;
    for (int d = -r; d <= r; d++) {
        int off = refl(y0 + d, HH) * WW;
        s0 += p0[off]; s1 += p1[off];
    }
    float* pt = g_h2 + b*HWSZ + x;   // t_final
    for (int y = y0; y < y0 + SEG; y++) {
        float tf = (s0*inv) * pg[y*WW] + (s1*inv);
        tf = fminf(fmaxf(tf, 0.1f), 1.0f);
        pt[y*WW] = tf;
        int ya = refl(y + 1 + r, HH) * WW;
        int ys = refl(y - r, HH) * WW;
        s0 += p0[ya] - p0[ys];
        s1 += p1[ya] - p1[ys];
    }
}

// ============ K5: restoration J + stage-1 histogram (key>>20), float4 ============
__global__ __launch_bounds__(256) void k_J_hist(const float* __restrict__ img,
                                                const float* __restrict__ atm) {
    __shared__ unsigned sh[4096];
    int tid = threadIdx.x;
    for (int i = tid; i < 4096; i += 256) sh[i] = 0;
    __syncthreads();
    int bc = blockIdx.y;
    int b = bc / 3;
    float A = atm[bc];
    size_t base = (size_t)bc * HWSZ + (size_t)blockIdx.x * 4096;
    const float4* ip = (const float4*)(img + base);
    const float4* tp = (const float4*)(g_h2 + (size_t)b * HWSZ + (size_t)blockIdx.x * 4096);
    float4* Jp = (float4*)(g_J + base);
    #pragma unroll
    for (int i = 0; i < 4; i++) {
        int o = i*256 + tid;
        float4 iv = ip[o];
        float4 tf = tp[o];
        float4 Jv;
        Jv.x = fminf(fmaxf((iv.x - A) / (tf.x + 1e-8f) + A, 0.0f), 1.0f);
        Jv.y = fminf(fmaxf((iv.y - A) / (tf.y + 1e-8f) + A, 0.0f), 1.0f);
        Jv.z = fminf(fmaxf((iv.z - A) / (tf.z + 1e-8f) + A, 0.0f), 1.0f);
        Jv.w = fminf(fmaxf((iv.w - A) / (tf.w + 1e-8f) + A, 0.0f), 1.0f);
        Jp[o] = Jv;
        atomicAdd(&sh[__float_as_uint(Jv.x) >> 20], 1u);
        atomicAdd(&sh[__float_as_uint(Jv.y) >> 20], 1u);
        atomicAdd(&sh[__float_as_uint(Jv.z) >> 20], 1u);
        atomicAdd(&sh[__float_as_uint(Jv.w) >> 20], 1u);
    }
    __syncthreads();
    for (int i = tid; i < 4096; i += 256)
        if (sh[i]) atomicAdd(&g_hist1[bc][i], sh[i]);
}

// ============ K6: stage-1 select (+ zero hist2) ============
__global__ void k_sel1(const float* __restrict__ Llow,
                       const float* __restrict__ Lhigh) {
    int bc = blockIdx.x;
    int b = bc / 3;
    // zero hist2 for this channel (accumulated later in k_hist2)
    {
        unsigned* h2 = &g_hist2[bc][0][0];
        for (int i = threadIdx.x; i < 8192; i += 256) h2[i] = 0;
    }
    __shared__ unsigned part[256];
    for (int slot = 0; slot < 2; slot++) {
        float Lv = (slot == 0) ? Llow[b] : Lhigh[b];
        float qf = (Lv / 100.0f) * (float)HWSZ;
        int tgt = (int)qf;
        if (tgt < 0) tgt = 0;
        if (tgt > HWSZ - 1) tgt = HWSZ - 1;
        const unsigned* h = g_hist1[bc];
        unsigned s = 0;
        for (int j = 0; j < 16; j++) s += h[threadIdx.x*16 + j];
        part[threadIdx.x] = s;
        __syncthreads();
        if (threadIdx.x == 0) {
            unsigned cum = 0;
            int slice = 0;
            for (; slice < 256; slice++) {
                if (cum + part[slice] > (unsigned)tgt) break;
                cum += part[slice];
            }
            int bin = slice * 16;
            for (;; bin++) {
                if (cum + h[bin] > (unsigned)tgt) break;
                cum += h[bin];
            }
            g_bin1[bc][slot]  = (unsigned)bin;
            g_rank1[bc][slot] = (unsigned)tgt - cum;
        }
        __syncthreads();
    }
}

// ============ K7: stage-2 histogram, float4 ============
__global__ __launch_bounds__(256) void k_hist2() {
    __shared__ unsigned shL[4096], shH[4096];
    int tid = threadIdx.x;
    for (int i = tid; i < 4096; i += 256) { shL[i] = 0; shH[i] = 0; }
    __syncthreads();
    int bc = blockIdx.y;
    unsigned binL = g_bin1[bc][0];
    unsigned binH = g_bin1[bc][1];
    const float4* Jp = (const float4*)(g_J + (size_t)bc * HWSZ + (size_t)blockIdx.x * 4096);
    #pragma unroll
    for (int i = 0; i < 4; i++) {
        float4 v = Jp[i*256 + tid];
        #pragma unroll
        for (int j = 0; j < 4; j++) {
            unsigned key = __float_as_uint(((const float*)&v)[j]);
            unsigned t12 = key >> 20;
            unsigned sub = (key >> 8) & 0xFFFu;
            if (t12 == binL) atomicAdd(&shL[sub], 1u);
            if (t12 == binH) atomicAdd(&shH[sub], 1u);
        }
    }
    __syncthreads();
    for (int i = tid; i < 4096; i += 256) {
        if (shL[i]) atomicAdd(&g_hist2[bc][0][i], shL[i]);
        if (shH[i]) atomicAdd(&g_hist2[bc][1][i], shH[i]);
    }
}

// ============ K8: stage-2 select (+ zero hist3) ============
__global__ void k_sel2() {
    int bc = blockIdx.x;
    {
        unsigned* h3 = &g_hist3[bc][0][0];
        for (int i = threadIdx.x; i < 512; i += 256) h3[i] = 0;
    }
    __shared__ unsigned part[256];
    for (int slot = 0; slot < 2; slot++) {
        unsigned tgt = g_rank1[bc][slot];
        const unsigned* h = g_hist2[bc][slot];
        unsigned s = 0;
        for (int j = 0; j < 16; j++) s += h[threadIdx.x*16 + j];
        part[threadIdx.x] = s;
        __syncthreads();
        if (threadIdx.x == 0) {
            unsigned cum = 0;
            int slice = 0;
            for (; slice < 256; slice++) {
                if (cum + part[slice] > tgt) break;
                cum += part[slice];
            }
            int bin = slice * 16;
            for (;; bin++) {
                if (cum + h[bin] > tgt) break;
                cum += h[bin];
            }
            g_pre2[bc][slot]  = (g_bin1[bc][slot] << 12) | (unsigned)bin;
            g_rank2[bc][slot] = tgt - cum;
        }
        __syncthreads();
    }
}

// ============ K9: stage-3 histogram, float4 ============
__global__ __launch_bounds__(256) void k_hist3() {
    __shared__ unsigned shL[256], shH[256];
    int tid = threadIdx.x;
    shL[tid] = 0; shH[tid] = 0;
    __syncthreads();
    int bc = blockIdx.y;
    unsigned preL = g_pre2[bc][0];
    unsigned preH = g_pre2[bc][1];
    const float4* Jp = (const float4*)(g_J + (size_t)bc * HWSZ + (size_t)blockIdx.x * 4096);
    #pragma unroll
    for (int i = 0; i < 4; i++) {
        float4 v = Jp[i*256 + tid];
        #pragma unroll
        for (int j = 0; j < 4; j++) {
            unsigned key = __float_as_uint(((const float*)&v)[j]);
            unsigned pre = key >> 8;
            unsigned sub = key & 0xFFu;
            if (pre == preL) atomicAdd(&shL[sub], 1u);
            if (pre == preH) atomicAdd(&shH[sub], 1u);
        }
    }
    __syncthreads();
    if (shL[tid]) atomicAdd(&g_hist3[bc][0][tid], shL[tid]);
    if (shH[tid]) atomicAdd(&g_hist3[bc][1][tid], shH[tid]);
}

// ============ K10: final select ============
__global__ void k_sel3() {
    int bc = blockIdx.x;
    if (threadIdx.x == 0) {
        for (int slot = 0; slot < 2; slot++) {
            unsigned tgt = g_rank2[bc][slot];
            const unsigned* h = g_hist3[bc][slot];
            unsigned cum = 0;
            int bin = 0;
            for (; bin < 256; bin++) {
                if (cum + h[bin] > tgt) break;
                cum += h[bin];
            }
            unsigned key = (g_pre2[bc][slot] << 8) | (unsigned)bin;
            g_pvals[bc][slot] = __uint_as_float(key);
        }
    }
}

// ============ K11: final normalize, float4 ============
__global__ __launch_bounds__(256) void k_out(float* __restrict__ out) {
    int idx4 = blockIdx.x * 256 + threadIdx.x;
    if (idx4 >= (3*NPLANE)/4) return;
    int bc = idx4 >> 16;                 // 65536 float4 per (b,c) plane
    float pl = g_pvals[bc][0];
    float ph = g_pvals[bc][1];
    float denom = 1.0f / (ph - pl + 1e-8f);
    float4 Jv = ((const float4*)g_J)[idx4];
    float4 o;
    o.x = fminf(fmaxf((fminf(fmaxf(Jv.x, pl), ph) - pl) * denom, 0.0f), 1.0f);
    o.y = fminf(fmaxf((fminf(fmaxf(Jv.y, pl), ph) - pl) * denom, 0.0f), 1.0f);
    o.z = fminf(fmaxf((fminf(fmaxf(Jv.z, pl), ph) - pl) * denom, 0.0f), 1.0f);
    o.w = fminf(fmaxf((fminf(fmaxf(Jv.w, pl), ph) - pl) * denom, 0.0f), 1.0f);
    ((float4*)out)[idx4] = o;
}

// ---------------- launch ----------------
extern "C" void kernel_launch(void* const* d_in, const int* in_sizes, int n_in,
                              void* d_out, int out_size) {
    const float* img   = (const float*)d_in[0];
    const float* omega = (const float*)d_in[1];
    const float* atm   = (const float*)d_in[2];
    const float* Llow  = (const float*)d_in[3];
    const float* Lhigh = (const float*)d_in[4];
    const int*   rp    = (const int*)d_in[5];
    float* out = (float*)d_out;

    (void)in_sizes; (void)n_in; (void)out_size;

    k_front<<<BN*HH, 128>>>(img, omega, atm, rp);
    k_vbox4<<<(BN*WW*(HH/SEG))/256, 256>>>(rp);
    k_hbox2<<<BN*HH, 128>>>(rp);
    k_vbox2<<<(BN*WW*(HH/SEG))/256, 256>>>(rp);
    dim3 gJ(HWSZ/4096, NCH);
    k_J_hist<<<gJ, 256>>>(img, atm);
    k_sel1<<<NCH, 256>>>(Llow, Lhigh);
    k_hist2<<<gJ, 256>>>();
    k_sel2<<<NCH, 256>>>();
    k_hist3<<<gJ, 256>>>();
    k_sel3<<<NCH, 32>>>();
    k_out<<<((3*NPLANE)/4 + 255)/256, 256>>>(out);
}

// round 4
// speedup vs baseline: 1.5880x; 1.3119x over previous
#include <cuda_runtime.h>
#include <cstdint>

// ---------------- problem constants ----------------
#define WW 512
#define HH 512
#define HWSZ (512*512)          // 262144
#define BN 8
#define NPLANE (BN*HWSZ)        // 2,097,152
#define NCH 24                  // B*3

// ---------------- scratch (device globals; no allocs allowed) ----------------
__device__ float g_a[NPLANE];
__device__ float g_b[NPLANE];
__device__ float g_gray[NPLANE];
__device__ float g_h0[NPLANE];
__device__ float g_h1[NPLANE];
__device__ float g_h2[NPLANE];      // later t_final
__device__ float g_h3[NPLANE];
__device__ float g_J[3*NPLANE];

__device__ unsigned g_hist1[NCH][4096];
__device__ unsigned g_hist2[NCH][2][4096];
__device__ unsigned g_hist3[NCH][2][256];
__device__ unsigned g_bin1[NCH][2];
__device__ unsigned g_rank1[NCH][2];
__device__ unsigned g_pre2[NCH][2];
__device__ unsigned g_rank2[NCH][2];
__device__ float    g_pvals[NCH][2];

__device__ __forceinline__ int refl(int i, int n) {
    i = (i < 0) ? -i : i;
    return (i >= n) ? (2*n - 2 - i) : i;
}
__device__ __forceinline__ int clampr(int r) {
    if (r < 1) r = 1;
    if (r > 50) r = 50;
    return r;
}

// ============ K1: fused t0/gray/tg + horizontal box of 4 streams ============
__global__ __launch_bounds__(128) void k_front(const float* __restrict__ img,
                                               const float* __restrict__ omega,
                                               const float* __restrict__ atm,
                                               const int* __restrict__ rp) {
    int r = clampr(rp[0]);
    int row = blockIdx.x;
    int b = row >> 9, y = row & 511;

    // zero hist1: 24*4096 entries over 4096 blocks = 24 each
    {
        unsigned* h1 = &g_hist1[0][0];
        int base = row * 24;
        for (int i = threadIdx.x; i < 24; i += 128) h1[base + i] = 0;
    }

    __shared__ float t0p[512], t0c[512];
    __shared__ float sg[612], st[612], sgt[612], sgg[612];

    float om = omega[b];
    float a0 = atm[b*3+0] + 1e-8f;
    float a1 = atm[b*3+1] + 1e-8f;
    float a2 = atm[b*3+2] + 1e-8f;
    const float* ib = img + (size_t)b * 3 * HWSZ;
    int yp = (y == 0) ? 0 : y - 1;
    int rowbase = b * HWSZ + y * WW;

    for (int x = threadIdx.x; x < 512; x += 128) {
        float rv = ib[yp*WW + x], gv = ib[HWSZ + yp*WW + x], bv = ib[2*HWSZ + yp*WW + x];
        float dark = fminf(rv/a0, fminf(gv/a1, bv/a2));
        t0p[x] = 1.0f - om * dark;
        float rc = ib[y*WW + x], gc = ib[HWSZ + y*WW + x], bc = ib[2*HWSZ + y*WW + x];
        float darkc = fminf(rc/a0, fminf(gc/a1, bc/a2));
        t0c[x] = 1.0f - om * darkc;
        float gy = 0.299f*rc + 0.587f*gc + 0.114f*bc;
        sg[r + x] = gy;
        g_gray[rowbase + x] = gy;
    }
    __syncthreads();

    for (int x = threadIdx.x; x < 512; x += 128) {
        float txv = (x == 0) ? t0p[0]
                             : t0p[x-1] * expf(-fabsf(t0p[x] - t0p[x-1]));
        float tgv = (y == 0) ? txv
                             : txv * expf(-fabsf(t0c[x] - t0p[x]));
        st[r + x] = tgv;
    }
    __syncthreads();

    for (int i = threadIdx.x; i < r; i += 128) {
        sg[i] = sg[r + (r - i)];
        st[i] = st[r + (r - i)];
        sg[r + 512 + i] = sg[r + 510 - i];
        st[r + 512 + i] = st[r + 510 - i];
    }
    __syncthreads();

    int pw = 512 + 2*r;
    for (int i = threadIdx.x; i < pw; i += 128) {
        float g = sg[i], t = st[i];
        sgt[i] = g * t;
        sgg[i] = g * g;
    }
    __syncthreads();

    int x0 = threadIdx.x * 4;
    int k = 2*r + 1;
    float s0 = 0.f, s1 = 0.f, s2 = 0.f, s3 = 0.f;
    for (int d = 0; d < k; d++) {
        s0 += sg[x0+d]; s1 += st[x0+d]; s2 += sgt[x0+d]; s3 += sgg[x0+d];
    }
    float4 o0, o1, o2, o3;
    o0.x = s0; o1.x = s1; o2.x = s2; o3.x = s3;
    #pragma unroll
    for (int j = 1; j < 4; j++) {
        int add = x0 + k - 1 + j, sub = x0 + j - 1;
        s0 += sg[add] - sg[sub];
        s1 += st[add] - st[sub];
        s2 += sgt[add] - sgt[sub];
        s3 += sgg[add] - sgg[sub];
        ((float*)&o0)[j] = s0; ((float*)&o1)[j] = s1;
        ((float*)&o2)[j] = s2; ((float*)&o3)[j] = s3;
    }
    int base = rowbase + x0;
    *(float4*)(g_h0 + base) = o0;
    *(float4*)(g_h1 + base) = o1;
    *(float4*)(g_h2 + base) = o2;
    *(float4*)(g_h3 + base) = o3;
}

// ============ K2: vertical box (sliding, SEG=16) + a,b ============
#define SEG 16
#define NSEG (HH/SEG)           // 32
__global__ __launch_bounds__(256) void k_vbox4(const int* __restrict__ rp) {
    int r = clampr(rp[0]);
    int k = 2*r + 1;
    float inv = 1.0f / ((float)k * (float)k);
    int t = blockIdx.x * blockDim.x + threadIdx.x;
    int x = t & 511;
    int q = t >> 9;
    int b = q & 7;
    int seg = q >> 3;
    int y0 = seg * SEG;
    const float* p0 = g_h0 + b*HWSZ + x;
    const float* p1 = g_h1 + b*HWSZ + x;
    const float* p2 = g_h2 + b*HWSZ + x;
    const float* p3 = g_h3 + b*HWSZ + x;
    float s0 = 0.f, s1 = 0.f, s2 = 0.f, s3 = 0.f;
    bool interior = (y0 - r >= 0) && (y0 + SEG + r < HH);
    if (interior) {
        for (int d = -r; d <= r; d++) {
            int off = (y0 + d) * WW;
            s0 += p0[off]; s1 += p1[off]; s2 += p2[off]; s3 += p3[off];
        }
    } else {
        for (int d = -r; d <= r; d++) {
            int off = refl(y0 + d, HH) * WW;
            s0 += p0[off]; s1 += p1[off]; s2 += p2[off]; s3 += p3[off];
        }
    }
    float* pa = g_a + b*HWSZ + x;
    float* pb = g_b + b*HWSZ + x;
    if (interior) {
        #pragma unroll 4
        for (int y = y0; y < y0 + SEG; y++) {
            float mI  = s0*inv, mp  = s1*inv;
            float mIp = s2*inv, mII = s3*inv;
            float a = (mIp - mI*mp) / ((mII - mI*mI) + 0.5f);
            pa[y*WW] = a;
            pb[y*WW] = mp - a*mI;
            int ya = (y + 1 + r) * WW;
            int ys = (y - r) * WW;
            s0 += p0[ya] - p0[ys];
            s1 += p1[ya] - p1[ys];
            s2 += p2[ya] - p2[ys];
            s3 += p3[ya] - p3[ys];
        }
    } else {
        for (int y = y0; y < y0 + SEG; y++) {
            float mI  = s0*inv, mp  = s1*inv;
            float mIp = s2*inv, mII = s3*inv;
            float a = (mIp - mI*mp) / ((mII - mI*mI) + 0.5f);
            pa[y*WW] = a;
            pb[y*WW] = mp - a*mI;
            int ya = refl(y + 1 + r, HH) * WW;
            int ys = refl(y - r, HH) * WW;
            s0 += p0[ya] - p0[ys];
            s1 += p1[ya] - p1[ys];
            s2 += p2[ya] - p2[ys];
            s3 += p3[ya] - p3[ys];
        }
    }
}

// ============ K3: horizontal box of {a,b} ============
__global__ __launch_bounds__(128) void k_hbox2(const int* __restrict__ rp) {
    int r = clampr(rp[0]);
    int row = blockIdx.x;
    int b = row >> 9, y = row & 511;
    __shared__ float sa[612], sb[612];
    int rowbase = b * HWSZ + y * WW;
    for (int x = threadIdx.x; x < 512; x += 128) {
        sa[r + x] = g_a[rowbase + x];
        sb[r + x] = g_b[rowbase + x];
    }
    __syncthreads();
    for (int i = threadIdx.x; i < r; i += 128) {
        sa[i] = sa[r + (r - i)];
        sb[i] = sb[r + (r - i)];
        sa[r + 512 + i] = sa[r + 510 - i];
        sb[r + 512 + i] = sb[r + 510 - i];
    }
    __syncthreads();
    int x0 = threadIdx.x * 4;
    int k = 2*r + 1;
    float s0 = 0.f, s1 = 0.f;
    for (int d = 0; d < k; d++) { s0 += sa[x0+d]; s1 += sb[x0+d]; }
    float4 o0, o1;
    o0.x = s0; o1.x = s1;
    #pragma unroll
    for (int j = 1; j < 4; j++) {
        int add = x0 + k - 1 + j, sub = x0 + j - 1;
        s0 += sa[add] - sa[sub];
        s1 += sb[add] - sb[sub];
        ((float*)&o0)[j] = s0; ((float*)&o1)[j] = s1;
    }
    *(float4*)(g_h0 + rowbase + x0) = o0;
    *(float4*)(g_h1 + rowbase + x0) = o1;
}

// ============ K4: vertical box of {a,b} (SEG=16) + t_final ============
__global__ __launch_bounds__(256) void k_vbox2(const int* __restrict__ rp) {
    int r = clampr(rp[0]);
    int k = 2*r + 1;
    float inv = 1.0f / ((float)k * (float)k);
    int t = blockIdx.x * blockDim.x + threadIdx.x;
    int x = t & 511;
    int q = t >> 9;
    int b = q & 7;
    int seg = q >> 3;
    int y0 = seg * SEG;
    const float* p0 = g_h0 + b*HWSZ + x;
    const float* p1 = g_h1 + b*HWSZ + x;
    const float* pg = g_gray + b*HWSZ + x;
    float s0 = 0.f, s1 = 0.f;
    bool interior = (y0 - r >= 0) && (y0 + SEG + r < HH);
    if (interior) {
        for (int d = -r; d <= r; d++) {
            int off = (y0 + d) * WW;
            s0 += p0[off]; s1 += p1[off];
        }
    } else {
        for (int d = -r; d <= r; d++) {
            int off = refl(y0 + d, HH) * WW;
            s0 += p0[off]; s1 += p1[off];
        }
    }
    float* pt = g_h2 + b*HWSZ + x;   // t_final
    if (interior) {
        #pragma unroll 4
        for (int y = y0; y < y0 + SEG; y++) {
            float tf = (s0*inv) * pg[y*WW] + (s1*inv);
            pt[y*WW] = fminf(fmaxf(tf, 0.1f), 1.0f);
            int ya = (y + 1 + r) * WW;
            int ys = (y - r) * WW;
            s0 += p0[ya] - p0[ys];
            s1 += p1[ya] - p1[ys];
        }
    } else {
        for (int y = y0; y < y0 + SEG; y++) {
            float tf = (s0*inv) * pg[y*WW] + (s1*inv);
            pt[y*WW] = fminf(fmaxf(tf, 0.1f), 1.0f);
            int ya = refl(y + 1 + r, HH) * WW;
            int ys = refl(y - r, HH) * WW;
            s0 += p0[ya] - p0[ys];
            s1 += p1[ya] - p1[ys];
        }
    }
}

// ============ K5: restoration J + stage-1 histogram ============
__global__ __launch_bounds__(256) void k_J_hist(const float* __restrict__ img,
                                                const float* __restrict__ atm) {
    __shared__ unsigned sh[4096];
    int tid = threadIdx.x;
    for (int i = tid; i < 4096; i += 256) sh[i] = 0;
    __syncthreads();
    int bc = blockIdx.y;
    int b = bc / 3;
    float A = atm[bc];
    size_t base = (size_t)bc * HWSZ + (size_t)blockIdx.x * 4096;
    const float4* ip = (const float4*)(img + base);
    const float4* tp = (const float4*)(g_h2 + (size_t)b * HWSZ + (size_t)blockIdx.x * 4096);
    float4* Jp = (float4*)(g_J + base);
    #pragma unroll
    for (int i = 0; i < 4; i++) {
        int o = i*256 + tid;
        float4 iv = ip[o];
        float4 tf = tp[o];
        float4 Jv;
        Jv.x = fminf(fmaxf((iv.x - A) / (tf.x + 1e-8f) + A, 0.0f), 1.0f);
        Jv.y = fminf(fmaxf((iv.y - A) / (tf.y + 1e-8f) + A, 0.0f), 1.0f);
        Jv.z = fminf(fmaxf((iv.z - A) / (tf.z + 1e-8f) + A, 0.0f), 1.0f);
        Jv.w = fminf(fmaxf((iv.w - A) / (tf.w + 1e-8f) + A, 0.0f), 1.0f);
        Jp[o] = Jv;
        atomicAdd(&sh[__float_as_uint(Jv.x) >> 20], 1u);
        atomicAdd(&sh[__float_as_uint(Jv.y) >> 20], 1u);
        atomicAdd(&sh[__float_as_uint(Jv.z) >> 20], 1u);
        atomicAdd(&sh[__float_as_uint(Jv.w) >> 20], 1u);
    }
    __syncthreads();
    for (int i = tid; i < 4096; i += 256)
        if (sh[i]) atomicAdd(&g_hist1[bc][i], sh[i]);
}

// ============ K6: stage-1 select (+ zero hist2) ============
__global__ void k_sel1(const float* __restrict__ Llow,
                       const float* __restrict__ Lhigh) {
    int bc = blockIdx.x;
    int b = bc / 3;
    {
        unsigned* h2 = &g_hist2[bc][0][0];
        for (int i = threadIdx.x; i < 8192; i += 256) h2[i] = 0;
    }
    __shared__ unsigned part[256];
    for (int slot = 0; slot < 2; slot++) {
        float Lv = (slot == 0) ? Llow[b] : Lhigh[b];
        float qf = (Lv / 100.0f) * (float)HWSZ;
        int tgt = (int)qf;
        if (tgt < 0) tgt = 0;
        if (tgt > HWSZ - 1) tgt = HWSZ - 1;
        const unsigned* h = g_hist1[bc];
        unsigned s = 0;
        for (int j = 0; j < 16; j++) s += h[threadIdx.x*16 + j];
        part[threadIdx.x] = s;
        __syncthreads();
        if (threadIdx.x == 0) {
            unsigned cum = 0;
            int slice = 0;
            for (; slice < 256; slice++) {
                if (cum + part[slice] > (unsigned)tgt) break;
                cum += part[slice];
            }
            int bin = slice * 16;
            for (;; bin++) {
                if (cum + h[bin] > (unsigned)tgt) break;
                cum += h[bin];
            }
            g_bin1[bc][slot]  = (unsigned)bin;
            g_rank1[bc][slot] = (unsigned)tgt - cum;
        }
        __syncthreads();
    }
}

// ============ K7: stage-2 histogram ============
__global__ __launch_bounds__(256) void k_hist2() {
    __shared__ unsigned shL[4096], shH[4096];
    int tid = threadIdx.x;
    for (int i = tid; i < 4096; i += 256) { shL[i] = 0; shH[i] = 0; }
    __syncthreads();
    int bc = blockIdx.y;
    unsigned binL = g_bin1[bc][0];
    unsigned binH = g_bin1[bc][1];
    const float4* Jp = (const float4*)(g_J + (size_t)bc * HWSZ + (size_t)blockIdx.x * 4096);
    #pragma unroll
    for (int i = 0; i < 4; i++) {
        float4 v = Jp[i*256 + tid];
        #pragma unroll
        for (int j = 0; j < 4; j++) {
            unsigned key = __float_as_uint(((const float*)&v)[j]);
            unsigned t12 = key >> 20;
            unsigned sub = (key >> 8) & 0xFFFu;
            if (t12 == binL) atomicAdd(&shL[sub], 1u);
            if (t12 == binH) atomicAdd(&shH[sub], 1u);
        }
    }
    __syncthreads();
    for (int i = tid; i < 4096; i += 256) {
        if (shL[i]) atomicAdd(&g_hist2[bc][0][i], shL[i]);
        if (shH[i]) atomicAdd(&g_hist2[bc][1][i], shH[i]);
    }
}

// ============ K8: stage-2 select (+ zero hist3) ============
__global__ void k_sel2() {
    int bc = blockIdx.x;
    {
        unsigned* h3 = &g_hist3[bc][0][0];
        for (int i = threadIdx.x; i < 512; i += 256) h3[i] = 0;
    }
    __shared__ unsigned part[256];
    for (int slot = 0; slot < 2; slot++) {
        unsigned tgt = g_rank1[bc][slot];
        const unsigned* h = g_hist2[bc][slot];
        unsigned s = 0;
        for (int j = 0; j < 16; j++) s += h[threadIdx.x*16 + j];
        part[threadIdx.x] = s;
        __syncthreads();
        if (threadIdx.x == 0) {
            unsigned cum = 0;
            int slice = 0;
            for (; slice < 256; slice++) {
                if (cum + part[slice] > tgt) break;
                cum += part[slice];
            }
            int bin = slice * 16;
            for (;; bin++) {
                if (cum + h[bin] > tgt) break;
                cum += h[bin];
            }
            g_pre2[bc][slot]  = (g_bin1[bc][slot] << 12) | (unsigned)bin;
            g_rank2[bc][slot] = tgt - cum;
        }
        __syncthreads();
    }
}

// ============ K9: stage-3 histogram ============
__global__ __launch_bounds__(256) void k_hist3() {
    __shared__ unsigned shL[256], shH[256];
    int tid = threadIdx.x;
    shL[tid] = 0; shH[tid] = 0;
    __syncthreads();
    int bc = blockIdx.y;
    unsigned preL = g_pre2[bc][0];
    unsigned preH = g_pre2[bc][1];
    const float4* Jp = (const float4*)(g_J + (size_t)bc * HWSZ + (size_t)blockIdx.x * 4096);
    #pragma unroll
    for (int i = 0; i < 4; i++) {
        float4 v = Jp[i*256 + tid];
        #pragma unroll
        for (int j = 0; j < 4; j++) {
            unsigned key = __float_as_uint(((const float*)&v)[j]);
            unsigned pre = key >> 8;
            unsigned sub = key & 0xFFu;
            if (pre == preL) atomicAdd(&shL[sub], 1u);
            if (pre == preH) atomicAdd(&shH[sub], 1u);
        }
    }
    __syncthreads();
    if (shL[tid]) atomicAdd(&g_hist3[bc][0][tid], shL[tid]);
    if (shH[tid]) atomicAdd(&g_hist3[bc][1][tid], shH[tid]);
}

// ============ K10: final select ============
__global__ void k_sel3() {
    int bc = blockIdx.x;
    if (threadIdx.x == 0) {
        for (int slot = 0; slot < 2; slot++) {
            unsigned tgt = g_rank2[bc][slot];
            const unsigned* h = g_hist3[bc][slot];
            unsigned cum = 0;
            int bin = 0;
            for (; bin < 256; bin++) {
                if (cum + h[bin] > tgt) break;
                cum += h[bin];
            }
            unsigned key = (g_pre2[bc][slot] << 8) | (unsigned)bin;
            g_pvals[bc][slot] = __uint_as_float(key);
        }
    }
}

// ============ K11: final normalize ============
__global__ __launch_bounds__(256) void k_out(float* __restrict__ out) {
    int idx4 = blockIdx.x * 256 + threadIdx.x;
    if (idx4 >= (3*NPLANE)/4) return;
    int bc = idx4 >> 16;
    float pl = g_pvals[bc][0];
    float ph = g_pvals[bc][1];
    float denom = 1.0f / (ph - pl + 1e-8f);
    float4 Jv = ((const float4*)g_J)[idx4];
    float4 o;
    o.x = fminf(fmaxf((fminf(fmaxf(Jv.x, pl), ph) - pl) * denom, 0.0f), 1.0f);
    o.y = fminf(fmaxf((fminf(fmaxf(Jv.y, pl), ph) - pl) * denom, 0.0f), 1.0f);
    o.z = fminf(fmaxf((fminf(fmaxf(Jv.z, pl), ph) - pl) * denom, 0.0f), 1.0f);
    o.w = fminf(fmaxf((fminf(fmaxf(Jv.w, pl), ph) - pl) * denom, 0.0f), 1.0f);
    ((float4*)out)[idx4] = o;
}

// ---------------- launch ----------------
extern "C" void kernel_launch(void* const* d_in, const int* in_sizes, int n_in,
                              void* d_out, int out_size) {
    const float* img   = (const float*)d_in[0];
    const float* omega = (const float*)d_in[1];
    const float* atm   = (const float*)d_in[2];
    const float* Llow  = (const float*)d_in[3];
    const float* Lhigh = (const float*)d_in[4];
    const int*   rp    = (const int*)d_in[5];
    float* out = (float*)d_out;

    (void)in_sizes; (void)n_in; (void)out_size;

    k_front<<<BN*HH, 128>>>(img, omega, atm, rp);
    k_vbox4<<<(BN*WW*NSEG)/256, 256>>>(rp);
    k_hbox2<<<BN*HH, 128>>>(rp);
    k_vbox2<<<(BN*WW*NSEG)/256, 256>>>(rp);
    dim3 gJ(HWSZ/4096, NCH);
    k_J_hist<<<gJ, 256>>>(img, atm);
    k_sel1<<<NCH, 256>>>(Llow, Lhigh);
    k_hist2<<<gJ, 256>>>();
    k_sel2<<<NCH, 256>>>();
    k_hist3<<<gJ, 256>>>();
    k_sel3<<<NCH, 32>>>();
    k_out<<<((3*NPLANE)/4 + 255)/256, 256>>>(out);
}